// round 1
// baseline (speedup 1.0000x reference)
#include <cuda_runtime.h>
#include <cuda_bf16.h>

// Problem constants
#define PN   64
#define PTC  256
#define PK   32
#define PTK  64
#define PD   256
#define D4   (PD/4)          // 64 float4 per row
#define FULL_T (PTK + PTC)   // 320

// Scratch (device globals — no allocation allowed)
__device__ float g_ctx_use[PN * PD];
__device__ float g_know_use[PN * PK * PD];
__device__ int   g_cs[PN];

// ck_mask dtype probe: jax bool may arrive as 1-byte bool or int32.
// All-true int8 array -> first word 0x01010101 (high bytes set) => byte layout.
// int32 array of 0/1 -> first word 0 or 1 => word layout.
__device__ __forceinline__ bool ck_mask_at(const unsigned char* p, int idx) {
    unsigned int w0 = *(const unsigned int*)p;
    if ((w0 & 0xFFFFFF00u) != 0u) {
        return p[idx] != 0;                          // int8 bool layout
    } else {
        return ((const int*)p)[idx] != 0;            // int32 layout
    }
}

__device__ __forceinline__ float4 f4add(float4 a, float4 b) {
    return make_float4(a.x + b.x, a.y + b.y, a.z + b.z, a.w + b.w);
}

// ---------------------------------------------------------------------------
// Kernel 1: ragged segment-sum pooling.
// Blocks [0, N*K): know_use pooling over TK=64 tokens.
// Blocks [N*K, N*K+N): ctx_use pooling over TC=256 tokens.
// 64 threads/block, thread j owns float4 at d = 4j.
// ---------------------------------------------------------------------------
__global__ __launch_bounds__(64)
void pool_kernel(const int* __restrict__ src_tokens,
                 const int* __restrict__ know_tokens,
                 const unsigned char* __restrict__ ckm,
                 const float* __restrict__ embed)
{
    __shared__ int toks[PTC];
    const int j = threadIdx.x;              // 0..63
    const int b = blockIdx.x;
    const float4* __restrict__ e4 = (const float4*)embed;

    if (b < PN * PK) {
        const int n = b / PK;
        const int k = b % PK;
        // stage tokens
        if (j < PTK) toks[j] = know_tokens[(size_t)b * PTK + j];
        __syncthreads();
        const bool cm = ck_mask_at(ckm, n * PK + k);

        float4 acc = make_float4(0.f, 0.f, 0.f, 0.f);
        int len = 0;
        #pragma unroll 4
        for (int t = 0; t < PTK; t++) {
            int tok = toks[t];
            if (cm && tok != 0) {
                len++;
                acc = f4add(acc, e4[(size_t)tok * D4 + j]);
            }
        }
        float s = rsqrtf(256.0f * (float)max(len, 1));
        float4 r = make_float4(acc.x * s, acc.y * s, acc.z * s, acc.w * s);
        ((float4*)g_know_use)[(size_t)b * D4 + j] = r;
    } else {
        const int n = b - PN * PK;
        // stage 256 tokens with 64 threads
        #pragma unroll
        for (int i = 0; i < 4; i++) toks[j + 64 * i] = src_tokens[n * PTC + j + 64 * i];
        __syncthreads();

        float4 acc = make_float4(0.f, 0.f, 0.f, 0.f);
        int len = 0;
        #pragma unroll 4
        for (int t = 0; t < PTC; t++) {
            int tok = toks[t];
            if (tok != 0) {
                len++;
                acc = f4add(acc, e4[(size_t)tok * D4 + j]);
            }
        }
        float s = rsqrtf(256.0f * (float)max(len, 1));
        float4 r = make_float4(acc.x * s, acc.y * s, acc.z * s, acc.w * s);
        ((float4*)g_ctx_use)[(size_t)n * D4 + j] = r;
    }
}

// ---------------------------------------------------------------------------
// Kernel 2: ck_attn = know_use . ctx_use, argmax selection, write ck_attn out.
// One block per n, 256 threads (8 warps, warp w handles k = w, w+8, ...).
// ---------------------------------------------------------------------------
__global__ __launch_bounds__(256)
void attn_kernel(const int* __restrict__ cs_ids,
                 const int* __restrict__ use_cs_ids,
                 const unsigned char* __restrict__ ckm,
                 float* __restrict__ out_ck_attn)
{
    const int n = blockIdx.x;
    const int wid = threadIdx.x >> 5;
    const int lane = threadIdx.x & 31;
    __shared__ float scores[PK];

    const float* __restrict__ cu = g_ctx_use + (size_t)n * PD;
    for (int k = wid; k < PK; k += 8) {
        const float* __restrict__ ku = g_know_use + ((size_t)n * PK + k) * PD;
        float p = 0.f;
        #pragma unroll
        for (int i = lane; i < PD; i += 32) p += ku[i] * cu[i];
        #pragma unroll
        for (int o = 16; o; o >>= 1) p += __shfl_xor_sync(0xFFFFFFFFu, p, o);
        if (lane == 0) scores[k] = p;
    }
    __syncthreads();

    if (threadIdx.x == 0) {
        int use = *use_cs_ids;
        int best = 0;
        float bv = -__int_as_float(0x7f800000);  // -inf
        #pragma unroll
        for (int k = 0; k < PK; k++) {
            float v = ck_mask_at(ckm, n * PK + k) ? scores[k] : -__int_as_float(0x7f800000);
            if (v > bv) { bv = v; best = k; }   // first-max (strict >) matches jnp.argmax
        }
        g_cs[n] = use ? cs_ids[n] : best;
    }
    if (threadIdx.x < PK) {
        bool cm = ck_mask_at(ckm, n * PK + threadIdx.x);
        out_ck_attn[n * PK + threadIdx.x] = cm ? scores[threadIdx.x] : 0.0f;
    }
}

// ---------------------------------------------------------------------------
// Kernel 3: build full_enc [N, 320, 256] and full_mask [N, 320].
// One block per output row (n,t), 64 threads, float4 per thread.
// ---------------------------------------------------------------------------
__global__ __launch_bounds__(64)
void gather_kernel(const int* __restrict__ src_tokens,
                   const int* __restrict__ know_tokens,
                   const unsigned char* __restrict__ ckm,
                   const float* __restrict__ embed,
                   float* __restrict__ out_enc,
                   float* __restrict__ out_mask)
{
    const int r = blockIdx.x;            // 0 .. N*320-1
    const int n = r / FULL_T;
    const int t = r % FULL_T;
    const int j = threadIdx.x;

    int tok;
    bool m;
    if (t < PTK) {
        int cs = g_cs[n];
        tok = know_tokens[((size_t)n * PK + cs) * PTK + t];
        m = (tok != 0) && ck_mask_at(ckm, n * PK + cs);
    } else {
        tok = src_tokens[n * PTC + (t - PTK)];
        m = (tok != 0);
    }

    float4 v = make_float4(0.f, 0.f, 0.f, 0.f);
    if (m) v = ((const float4*)embed)[(size_t)tok * D4 + j];
    ((float4*)out_enc)[(size_t)r * D4 + j] = v;
    if (j == 0) out_mask[r] = m ? 1.0f : 0.0f;
}

// ---------------------------------------------------------------------------
extern "C" void kernel_launch(void* const* d_in, const int* in_sizes, int n_in,
                              void* d_out, int out_size)
{
    const int*           src_tokens  = (const int*)d_in[0];            // [N,TC]
    const int*           know_tokens = (const int*)d_in[1];            // [N,K,TK]
    const unsigned char* ck_mask     = (const unsigned char*)d_in[2];  // [N,K] bool
    const int*           cs_ids      = (const int*)d_in[3];            // [N]
    const int*           use_cs_ids  = (const int*)d_in[4];            // scalar
    const float*         embed       = (const float*)d_in[5];          // [V,D]

    float* out = (float*)d_out;
    float* out_enc     = out;                                   // N*320*256
    float* out_mask    = out + (size_t)PN * FULL_T * PD;        // N*320
    float* out_ck_attn = out_mask + (size_t)PN * FULL_T;        // N*K

    pool_kernel<<<PN * PK + PN, 64>>>(src_tokens, know_tokens, ck_mask, embed);
    attn_kernel<<<PN, 256>>>(cs_ids, use_cs_ids, ck_mask, out_ck_attn);
    gather_kernel<<<PN * FULL_T, 64>>>(src_tokens, know_tokens, ck_mask, embed,
                                       out_enc, out_mask);
}

// round 2
// speedup vs baseline: 1.3384x; 1.3384x over previous
#include <cuda_runtime.h>
#include <cuda_bf16.h>

// Problem constants
#define PN   64
#define PTC  256
#define PK   32
#define PTK  64
#define PD   256
#define D4   (PD/4)          // 64 float4 per row
#define FULL_T (PTK + PTC)   // 320

// Scratch (device globals — no allocation allowed)
__device__ float g_ctx_use[PN * PD];
__device__ float g_know_use[PN * PK * PD];
__device__ int   g_cs[PN];

// ck_mask dtype probe: jax bool may arrive as 1-byte bool or int32.
__device__ __forceinline__ bool ck_mask_at(const unsigned char* p, int idx) {
    unsigned int w0 = *(const unsigned int*)p;
    if ((w0 & 0xFFFFFF00u) != 0u) {
        return p[idx] != 0;                          // int8 bool layout
    } else {
        return ((const int*)p)[idx] != 0;            // int32 layout
    }
}

__device__ __forceinline__ float4 f4add(float4 a, float4 b) {
    return make_float4(a.x + b.x, a.y + b.y, a.z + b.z, a.w + b.w);
}

// ---------------------------------------------------------------------------
// Kernel 1: ragged segment-sum pooling, 256 threads/block.
// Thread layout: j = tid & 63 (owns float4 column), tq = tid >> 6 (token group).
// Blocks [0, N*K): know pooling, each tq handles 16 of 64 tokens.
// Blocks [N*K, N*K+N): ctx pooling, each tq handles 64 of 256 tokens.
// Partial sums reduced through shared memory.
// ---------------------------------------------------------------------------
__global__ __launch_bounds__(256)
void pool_kernel(const int* __restrict__ src_tokens,
                 const int* __restrict__ know_tokens,
                 const unsigned char* __restrict__ ckm,
                 const float* __restrict__ embed)
{
    __shared__ int    toks[PTC];
    __shared__ float4 part[4][D4];     // 4 KB
    __shared__ int    lenp[4];

    const int tid = threadIdx.x;
    const int j   = tid & 63;
    const int tq  = tid >> 6;
    const int b   = blockIdx.x;
    const float4* __restrict__ e4 = (const float4*)embed;

    float4 acc = make_float4(0.f, 0.f, 0.f, 0.f);
    int len = 0;
    float* dst;

    if (b < PN * PK) {
        const int n = b / PK;
        if (tid < PTK) toks[tid] = know_tokens[(size_t)b * PTK + tid];
        __syncthreads();
        const bool cm = ck_mask_at(ckm, n * PK + (b % PK));

        const int t0 = tq * 16;
        #pragma unroll
        for (int t = 0; t < 16; t++) {
            int tok = toks[t0 + t];
            if (cm && tok != 0) {
                len++;
                acc = f4add(acc, e4[(size_t)tok * D4 + j]);
            }
        }
        dst = g_know_use + (size_t)b * PD;
    } else {
        const int n = b - PN * PK;
        toks[tid] = src_tokens[n * PTC + tid];
        __syncthreads();

        const int t0 = tq * 64;
        #pragma unroll 8
        for (int t = 0; t < 64; t++) {
            int tok = toks[t0 + t];
            if (tok != 0) {
                len++;
                acc = f4add(acc, e4[(size_t)tok * D4 + j]);
            }
        }
        dst = g_ctx_use + (size_t)n * PD;
    }

    part[tq][j] = acc;
    if (j == 0) lenp[tq] = len;
    __syncthreads();

    if (tq == 0) {
        float4 a = f4add(f4add(part[0][j], part[1][j]),
                         f4add(part[2][j], part[3][j]));
        int L = lenp[0] + lenp[1] + lenp[2] + lenp[3];
        float s = rsqrtf(256.0f * (float)max(L, 1));
        ((float4*)dst)[j] = make_float4(a.x * s, a.y * s, a.z * s, a.w * s);
    }
}

// ---------------------------------------------------------------------------
// Kernel 2: ck_attn = know_use . ctx_use, argmax selection, write ck_attn out.
// One block per n, 256 threads (8 warps, warp w handles k = w, w+8, ...).
// ---------------------------------------------------------------------------
__global__ __launch_bounds__(256)
void attn_kernel(const int* __restrict__ cs_ids,
                 const int* __restrict__ use_cs_ids,
                 const unsigned char* __restrict__ ckm,
                 float* __restrict__ out_ck_attn)
{
    const int n = blockIdx.x;
    const int wid = threadIdx.x >> 5;
    const int lane = threadIdx.x & 31;
    __shared__ float scores[PK];

    const float* __restrict__ cu = g_ctx_use + (size_t)n * PD;
    for (int k = wid; k < PK; k += 8) {
        const float* __restrict__ ku = g_know_use + ((size_t)n * PK + k) * PD;
        float p = 0.f;
        #pragma unroll
        for (int i = lane; i < PD; i += 32) p += ku[i] * cu[i];
        #pragma unroll
        for (int o = 16; o; o >>= 1) p += __shfl_xor_sync(0xFFFFFFFFu, p, o);
        if (lane == 0) scores[k] = p;
    }
    __syncthreads();

    if (threadIdx.x == 0) {
        int use = *use_cs_ids;
        int best = 0;
        float bv = -__int_as_float(0x7f800000);  // -inf
        #pragma unroll
        for (int k = 0; k < PK; k++) {
            float v = ck_mask_at(ckm, n * PK + k) ? scores[k] : -__int_as_float(0x7f800000);
            if (v > bv) { bv = v; best = k; }   // first-max (strict >) matches jnp.argmax
        }
        g_cs[n] = use ? cs_ids[n] : best;
    }
    if (threadIdx.x < PK) {
        bool cm = ck_mask_at(ckm, n * PK + threadIdx.x);
        out_ck_attn[n * PK + threadIdx.x] = cm ? scores[threadIdx.x] : 0.0f;
    }
}

// ---------------------------------------------------------------------------
// Kernel 3: build full_enc [N, 320, 256] and full_mask [N, 320].
// 256 threads/block, 4 output rows per block (rq = tid>>6), float4 per thread.
// ---------------------------------------------------------------------------
__global__ __launch_bounds__(256)
void gather_kernel(const int* __restrict__ src_tokens,
                   const int* __restrict__ know_tokens,
                   const unsigned char* __restrict__ ckm,
                   const float* __restrict__ embed,
                   float* __restrict__ out_enc,
                   float* __restrict__ out_mask)
{
    const int tid = threadIdx.x;
    const int j   = tid & 63;
    const int r   = blockIdx.x * 4 + (tid >> 6);   // 0 .. N*320-1
    const int n = r / FULL_T;
    const int t = r % FULL_T;

    int tok;
    bool m;
    if (t < PTK) {
        int cs = g_cs[n];
        tok = know_tokens[((size_t)n * PK + cs) * PTK + t];
        m = (tok != 0) && ck_mask_at(ckm, n * PK + cs);
    } else {
        tok = src_tokens[n * PTC + (t - PTK)];
        m = (tok != 0);
    }

    float4 v = make_float4(0.f, 0.f, 0.f, 0.f);
    if (m) v = ((const float4*)embed)[(size_t)tok * D4 + j];
    ((float4*)out_enc)[(size_t)r * D4 + j] = v;
    if (j == 0) out_mask[r] = m ? 1.0f : 0.0f;
}

// ---------------------------------------------------------------------------
extern "C" void kernel_launch(void* const* d_in, const int* in_sizes, int n_in,
                              void* d_out, int out_size)
{
    const int*           src_tokens  = (const int*)d_in[0];            // [N,TC]
    const int*           know_tokens = (const int*)d_in[1];            // [N,K,TK]
    const unsigned char* ck_mask     = (const unsigned char*)d_in[2];  // [N,K] bool
    const int*           cs_ids      = (const int*)d_in[3];            // [N]
    const int*           use_cs_ids  = (const int*)d_in[4];            // scalar
    const float*         embed       = (const float*)d_in[5];          // [V,D]

    float* out = (float*)d_out;
    float* out_enc     = out;                                   // N*320*256
    float* out_mask    = out + (size_t)PN * FULL_T * PD;        // N*320
    float* out_ck_attn = out_mask + (size_t)PN * FULL_T;        // N*K

    pool_kernel<<<PN * PK + PN, 256>>>(src_tokens, know_tokens, ck_mask, embed);
    attn_kernel<<<PN, 256>>>(cs_ids, use_cs_ids, ck_mask, out_ck_attn);
    gather_kernel<<<(PN * FULL_T) / 4, 256>>>(src_tokens, know_tokens, ck_mask, embed,
                                              out_enc, out_mask);
}

// round 3
// speedup vs baseline: 1.4386x; 1.0749x over previous
#include <cuda_runtime.h>
#include <cuda_bf16.h>

// Problem constants
#define PN   64
#define PTC  256
#define PK   32
#define PTK  64
#define PD   256
#define D4   (PD/4)          // 64 float4 per row
#define FULL_T (PTK + PTC)   // 320

// Scratch (device globals — no allocation allowed)
__device__ float g_ctx_use[PN * PD];
__device__ float g_know_use[PN * PK * PD];
__device__ int   g_cs[PN];

// ck_mask dtype probe: jax bool may arrive as 1-byte bool or int32.
__device__ __forceinline__ bool ck_mask_at(const unsigned char* p, int idx) {
    unsigned int w0 = *(const unsigned int*)p;
    if ((w0 & 0xFFFFFF00u) != 0u) {
        return p[idx] != 0;                          // int8 bool layout
    } else {
        return ((const int*)p)[idx] != 0;            // int32 layout
    }
}

// ---------------------------------------------------------------------------
// Kernel 1: ragged segment-sum pooling, 256 threads/block, BRANCHLESS body.
// Thread layout: j = tid & 63 (owns float4 column), tq = tid >> 6 (token group).
// Blocks [0, N*K): know pooling, each tq handles 16 of 64 tokens.
// Blocks [N*K, N*K+N): ctx pooling, each tq handles 64 of 256 tokens.
// Always load embed[tok] (tok=0 row is valid + L1-hot), weight by (tok!=0).
// ---------------------------------------------------------------------------
__global__ __launch_bounds__(256)
void pool_kernel(const int* __restrict__ src_tokens,
                 const int* __restrict__ know_tokens,
                 const unsigned char* __restrict__ ckm,
                 const float* __restrict__ embed)
{
    __shared__ int    toks[PTC];
    __shared__ float4 part[4][D4];     // 4 KB
    __shared__ float  lenp[4];

    const int tid = threadIdx.x;
    const int j   = tid & 63;
    const int tq  = tid >> 6;
    const int b   = blockIdx.x;
    const float4* __restrict__ e4 = (const float4*)embed;

    float4 acc = make_float4(0.f, 0.f, 0.f, 0.f);
    float  lenf = 0.f;
    float* dst;

    if (b < PN * PK) {
        const int n = b / PK;
        if (tid < PTK) toks[tid] = know_tokens[(size_t)b * PTK + tid];
        __syncthreads();
        const float cmv = ck_mask_at(ckm, n * PK + (b % PK)) ? 1.0f : 0.0f;

        const int t0 = tq * 16;
        #pragma unroll
        for (int t = 0; t < 16; t++) {
            int   tok = toks[t0 + t];
            float w   = (tok != 0) ? 1.0f : 0.0f;
            float4 v  = e4[(size_t)tok * D4 + j];    // unconditional load
            acc.x = fmaf(w, v.x, acc.x);
            acc.y = fmaf(w, v.y, acc.y);
            acc.z = fmaf(w, v.z, acc.z);
            acc.w = fmaf(w, v.w, acc.w);
            lenf += w;
        }
        acc.x *= cmv; acc.y *= cmv; acc.z *= cmv; acc.w *= cmv;
        lenf *= cmv;
        dst = g_know_use + (size_t)b * PD;
    } else {
        const int n = b - PN * PK;
        toks[tid] = src_tokens[n * PTC + tid];
        __syncthreads();

        const int t0 = tq * 64;
        #pragma unroll 16
        for (int t = 0; t < 64; t++) {
            int   tok = toks[t0 + t];
            float w   = (tok != 0) ? 1.0f : 0.0f;
            float4 v  = e4[(size_t)tok * D4 + j];    // unconditional load
            acc.x = fmaf(w, v.x, acc.x);
            acc.y = fmaf(w, v.y, acc.y);
            acc.z = fmaf(w, v.z, acc.z);
            acc.w = fmaf(w, v.w, acc.w);
            lenf += w;
        }
        dst = g_ctx_use + (size_t)n * PD;
    }

    part[tq][j] = acc;
    if (j == 0) lenp[tq] = lenf;
    __syncthreads();

    if (tq == 0) {
        float4 p0 = part[0][j], p1 = part[1][j], p2 = part[2][j], p3 = part[3][j];
        float4 a = make_float4(p0.x + p1.x + p2.x + p3.x,
                               p0.y + p1.y + p2.y + p3.y,
                               p0.z + p1.z + p2.z + p3.z,
                               p0.w + p1.w + p2.w + p3.w);
        float L = lenp[0] + lenp[1] + lenp[2] + lenp[3];
        float s = rsqrtf(256.0f * fmaxf(L, 1.0f));
        ((float4*)dst)[j] = make_float4(a.x * s, a.y * s, a.z * s, a.w * s);
    }
}

// ---------------------------------------------------------------------------
// Kernel 2: ck_attn = know_use . ctx_use, argmax selection, write ck_attn out.
// One block per n, 256 threads (8 warps, warp w handles k = w, w+8, ...).
// ---------------------------------------------------------------------------
__global__ __launch_bounds__(256)
void attn_kernel(const int* __restrict__ cs_ids,
                 const int* __restrict__ use_cs_ids,
                 const unsigned char* __restrict__ ckm,
                 float* __restrict__ out_ck_attn)
{
    const int n = blockIdx.x;
    const int wid = threadIdx.x >> 5;
    const int lane = threadIdx.x & 31;
    __shared__ float scores[PK];

    const float* __restrict__ cu = g_ctx_use + (size_t)n * PD;
    for (int k = wid; k < PK; k += 8) {
        const float* __restrict__ ku = g_know_use + ((size_t)n * PK + k) * PD;
        float p = 0.f;
        #pragma unroll
        for (int i = lane; i < PD; i += 32) p += ku[i] * cu[i];
        #pragma unroll
        for (int o = 16; o; o >>= 1) p += __shfl_xor_sync(0xFFFFFFFFu, p, o);
        if (lane == 0) scores[k] = p;
    }
    __syncthreads();

    if (threadIdx.x == 0) {
        int use = *use_cs_ids;
        int best = 0;
        float bv = -__int_as_float(0x7f800000);  // -inf
        #pragma unroll
        for (int k = 0; k < PK; k++) {
            float v = ck_mask_at(ckm, n * PK + k) ? scores[k] : -__int_as_float(0x7f800000);
            if (v > bv) { bv = v; best = k; }   // first-max (strict >) matches jnp.argmax
        }
        g_cs[n] = use ? cs_ids[n] : best;
    }
    if (threadIdx.x < PK) {
        bool cm = ck_mask_at(ckm, n * PK + threadIdx.x);
        out_ck_attn[n * PK + threadIdx.x] = cm ? scores[threadIdx.x] : 0.0f;
    }
}

// ---------------------------------------------------------------------------
// Kernel 3: build full_enc [N, 320, 256] and full_mask [N, 320]. BRANCHLESS.
// 256 threads/block, 4 output rows per block (tid>>6), float4 per thread.
// ---------------------------------------------------------------------------
__global__ __launch_bounds__(256)
void gather_kernel(const int* __restrict__ src_tokens,
                   const int* __restrict__ know_tokens,
                   const unsigned char* __restrict__ ckm,
                   const float* __restrict__ embed,
                   float* __restrict__ out_enc,
                   float* __restrict__ out_mask)
{
    const int tid = threadIdx.x;
    const int j   = tid & 63;
    const int r   = blockIdx.x * 4 + (tid >> 6);   // 0 .. N*320-1
    const int n = r / FULL_T;
    const int t = r % FULL_T;

    int tok;
    bool m;
    if (t < PTK) {
        int cs = g_cs[n];
        tok = know_tokens[((size_t)n * PK + cs) * PTK + t];
        m = (tok != 0) && ck_mask_at(ckm, n * PK + cs);
    } else {
        tok = src_tokens[n * PTC + (t - PTK)];
        m = (tok != 0);
    }

    float w = m ? 1.0f : 0.0f;
    int row = m ? tok : 0;
    float4 v = ((const float4*)embed)[(size_t)row * D4 + j];   // unconditional load
    ((float4*)out_enc)[(size_t)r * D4 + j] =
        make_float4(w * v.x, w * v.y, w * v.z, w * v.w);
    if (j == 0) out_mask[r] = w;
}

// ---------------------------------------------------------------------------
extern "C" void kernel_launch(void* const* d_in, const int* in_sizes, int n_in,
                              void* d_out, int out_size)
{
    const int*           src_tokens  = (const int*)d_in[0];            // [N,TC]
    const int*           know_tokens = (const int*)d_in[1];            // [N,K,TK]
    const unsigned char* ck_mask     = (const unsigned char*)d_in[2];  // [N,K] bool
    const int*           cs_ids      = (const int*)d_in[3];            // [N]
    const int*           use_cs_ids  = (const int*)d_in[4];            // scalar
    const float*         embed       = (const float*)d_in[5];          // [V,D]

    float* out = (float*)d_out;
    float* out_enc     = out;                                   // N*320*256
    float* out_mask    = out + (size_t)PN * FULL_T * PD;        // N*320
    float* out_ck_attn = out_mask + (size_t)PN * FULL_T;        // N*K

    pool_kernel<<<PN * PK + PN, 256>>>(src_tokens, know_tokens, ck_mask, embed);
    attn_kernel<<<PN, 256>>>(cs_ids, use_cs_ids, ck_mask, out_ck_attn);
    gather_kernel<<<(PN * FULL_T) / 4, 256>>>(src_tokens, know_tokens, ck_mask, embed,
                                              out_enc, out_mask);
}

// round 4
// speedup vs baseline: 1.4539x; 1.0106x over previous
#include <cuda_runtime.h>
#include <cuda_bf16.h>

// Problem constants
#define PN   64
#define PTC  256
#define PK   32
#define PTK  64
#define PD   256
#define D4   (PD/4)          // 64 float4 per row
#define FULL_T (PTK + PTC)   // 320

// Scratch (device globals — no allocation allowed)
__device__ float g_ctx_use[PN * PD];
__device__ float g_know_use[PN * PK * PD];
__device__ int   g_cs[PN];

// ck_mask dtype probe: jax bool may arrive as 1-byte bool or int32.
__device__ __forceinline__ bool ck_mask_at(const unsigned char* p, int idx) {
    unsigned int w0 = *(const unsigned int*)p;
    if ((w0 & 0xFFFFFF00u) != 0u) {
        return p[idx] != 0;                          // int8 bool layout
    } else {
        return ((const int*)p)[idx] != 0;            // int32 layout
    }
}

// 8-wide batched accumulate: 8 independent LDG.128 in flight, then FMAs.
__device__ __forceinline__ void batch8(const float4* __restrict__ e4,
                                       const int* __restrict__ toks,
                                       int t0, int j,
                                       float4& acc, float& lenf)
{
    int tk[8];
    #pragma unroll
    for (int i = 0; i < 8; i++) tk[i] = toks[t0 + i];
    float4 v[8];
    #pragma unroll
    for (int i = 0; i < 8; i++) v[i] = e4[(size_t)tk[i] * D4 + j];
    #pragma unroll
    for (int i = 0; i < 8; i++) {
        float w = (tk[i] != 0) ? 1.0f : 0.0f;
        acc.x = fmaf(w, v[i].x, acc.x);
        acc.y = fmaf(w, v[i].y, acc.y);
        acc.z = fmaf(w, v[i].z, acc.z);
        acc.w = fmaf(w, v[i].w, acc.w);
        lenf += w;
    }
}

// ---------------------------------------------------------------------------
// Kernel 1: ragged segment-sum pooling, 256 threads/block, branchless,
// explicit 8-wide load batching for MLP.
// Thread layout: j = tid & 63 (float4 column), tq = tid >> 6 (token group).
// Blocks [0, N*K): know pooling (tq handles 16 of 64 tokens, 2 batches).
// Blocks [N*K, N*K+N): ctx pooling (tq handles 64 of 256 tokens, 8 batches).
// ---------------------------------------------------------------------------
__global__ __launch_bounds__(256)
void pool_kernel(const int* __restrict__ src_tokens,
                 const int* __restrict__ know_tokens,
                 const unsigned char* __restrict__ ckm,
                 const float* __restrict__ embed)
{
    __shared__ int    toks[PTC];
    __shared__ float4 part[4][D4];     // 4 KB
    __shared__ float  lenp[4];

    const int tid = threadIdx.x;
    const int j   = tid & 63;
    const int tq  = tid >> 6;
    const int b   = blockIdx.x;
    const float4* __restrict__ e4 = (const float4*)embed;

    float4 acc = make_float4(0.f, 0.f, 0.f, 0.f);
    float  lenf = 0.f;
    float* dst;

    if (b < PN * PK) {
        const int n = b / PK;
        if (tid < PTK) toks[tid] = know_tokens[(size_t)b * PTK + tid];
        __syncthreads();
        const float cmv = ck_mask_at(ckm, n * PK + (b % PK)) ? 1.0f : 0.0f;

        const int t0 = tq * 16;
        batch8(e4, toks, t0,     j, acc, lenf);
        batch8(e4, toks, t0 + 8, j, acc, lenf);

        acc.x *= cmv; acc.y *= cmv; acc.z *= cmv; acc.w *= cmv;
        lenf *= cmv;
        dst = g_know_use + (size_t)b * PD;
    } else {
        const int n = b - PN * PK;
        toks[tid] = src_tokens[n * PTC + tid];
        __syncthreads();

        const int t0 = tq * 64;
        #pragma unroll
        for (int bt = 0; bt < 8; bt++)
            batch8(e4, toks, t0 + bt * 8, j, acc, lenf);

        dst = g_ctx_use + (size_t)n * PD;
    }

    part[tq][j] = acc;
    if (j == 0) lenp[tq] = lenf;
    __syncthreads();

    if (tq == 0) {
        float4 p0 = part[0][j], p1 = part[1][j], p2 = part[2][j], p3 = part[3][j];
        float4 a = make_float4(p0.x + p1.x + p2.x + p3.x,
                               p0.y + p1.y + p2.y + p3.y,
                               p0.z + p1.z + p2.z + p3.z,
                               p0.w + p1.w + p2.w + p3.w);
        float L = lenp[0] + lenp[1] + lenp[2] + lenp[3];
        float s = rsqrtf(256.0f * fmaxf(L, 1.0f));
        ((float4*)dst)[j] = make_float4(a.x * s, a.y * s, a.z * s, a.w * s);
    }
}

// ---------------------------------------------------------------------------
// Kernel 2: ck_attn = know_use . ctx_use, argmax selection, write ck_attn out.
// One block per n, 256 threads (8 warps, warp w handles k = w, w+8, ...).
// ---------------------------------------------------------------------------
__global__ __launch_bounds__(256)
void attn_kernel(const int* __restrict__ cs_ids,
                 const int* __restrict__ use_cs_ids,
                 const unsigned char* __restrict__ ckm,
                 float* __restrict__ out_ck_attn)
{
    const int n = blockIdx.x;
    const int wid = threadIdx.x >> 5;
    const int lane = threadIdx.x & 31;
    __shared__ float scores[PK];

    const float* __restrict__ cu = g_ctx_use + (size_t)n * PD;
    for (int k = wid; k < PK; k += 8) {
        const float* __restrict__ ku = g_know_use + ((size_t)n * PK + k) * PD;
        float p = 0.f;
        #pragma unroll
        for (int i = lane; i < PD; i += 32) p += ku[i] * cu[i];
        #pragma unroll
        for (int o = 16; o; o >>= 1) p += __shfl_xor_sync(0xFFFFFFFFu, p, o);
        if (lane == 0) scores[k] = p;
    }
    __syncthreads();

    if (threadIdx.x == 0) {
        int use = *use_cs_ids;
        int best = 0;
        float bv = -__int_as_float(0x7f800000);  // -inf
        #pragma unroll
        for (int k = 0; k < PK; k++) {
            float v = ck_mask_at(ckm, n * PK + k) ? scores[k] : -__int_as_float(0x7f800000);
            if (v > bv) { bv = v; best = k; }   // first-max (strict >) matches jnp.argmax
        }
        g_cs[n] = use ? cs_ids[n] : best;
    }
    if (threadIdx.x < PK) {
        bool cm = ck_mask_at(ckm, n * PK + threadIdx.x);
        out_ck_attn[n * PK + threadIdx.x] = cm ? scores[threadIdx.x] : 0.0f;
    }
}

// ---------------------------------------------------------------------------
// Kernel 3: build full_enc [N, 320, 256] and full_mask [N, 320]. Branchless.
// 256 threads/block, 4 output rows per block (tid>>6), float4 per thread.
// ---------------------------------------------------------------------------
__global__ __launch_bounds__(256)
void gather_kernel(const int* __restrict__ src_tokens,
                   const int* __restrict__ know_tokens,
                   const unsigned char* __restrict__ ckm,
                   const float* __restrict__ embed,
                   float* __restrict__ out_enc,
                   float* __restrict__ out_mask)
{
    const int tid = threadIdx.x;
    const int j   = tid & 63;
    const int r   = blockIdx.x * 4 + (tid >> 6);   // 0 .. N*320-1
    const int n = r / FULL_T;
    const int t = r % FULL_T;

    int tok;
    bool m;
    if (t < PTK) {
        int cs = g_cs[n];
        tok = know_tokens[((size_t)n * PK + cs) * PTK + t];
        m = (tok != 0) && ck_mask_at(ckm, n * PK + cs);
    } else {
        tok = src_tokens[n * PTC + (t - PTK)];
        m = (tok != 0);
    }

    float w = m ? 1.0f : 0.0f;
    int row = m ? tok : 0;
    float4 v = ((const float4*)embed)[(size_t)row * D4 + j];   // unconditional load
    ((float4*)out_enc)[(size_t)r * D4 + j] =
        make_float4(w * v.x, w * v.y, w * v.z, w * v.w);
    if (j == 0) out_mask[r] = w;
}

// ---------------------------------------------------------------------------
extern "C" void kernel_launch(void* const* d_in, const int* in_sizes, int n_in,
                              void* d_out, int out_size)
{
    const int*           src_tokens  = (const int*)d_in[0];            // [N,TC]
    const int*           know_tokens = (const int*)d_in[1];            // [N,K,TK]
    const unsigned char* ck_mask     = (const unsigned char*)d_in[2];  // [N,K] bool
    const int*           cs_ids      = (const int*)d_in[3];            // [N]
    const int*           use_cs_ids  = (const int*)d_in[4];            // scalar
    const float*         embed       = (const float*)d_in[5];          // [V,D]

    float* out = (float*)d_out;
    float* out_enc     = out;                                   // N*320*256
    float* out_mask    = out + (size_t)PN * FULL_T * PD;        // N*320
    float* out_ck_attn = out_mask + (size_t)PN * FULL_T;        // N*K

    pool_kernel<<<PN * PK + PN, 256>>>(src_tokens, know_tokens, ck_mask, embed);
    attn_kernel<<<PN, 256>>>(cs_ids, use_cs_ids, ck_mask, out_ck_attn);
    gather_kernel<<<(PN * FULL_T) / 4, 256>>>(src_tokens, know_tokens, ck_mask, embed,
                                              out_enc, out_mask);
}

// round 5
// speedup vs baseline: 1.5709x; 1.0805x over previous
#include <cuda_runtime.h>
#include <cuda_bf16.h>

// Problem constants
#define PN   64
#define PTC  256
#define PK   32
#define PTK  64
#define PD   256
#define D4   (PD/4)          // 64 float4 per row
#define FULL_T (PTK + PTC)   // 320

// Scratch (device globals — no allocation allowed)
__device__ float g_ctx_use[PN * PD];
__device__ float g_know_use[PN * PK * PD];
__device__ int   g_cs[PN];

// ck_mask dtype probe: jax bool may arrive as 1-byte bool or int32.
__device__ __forceinline__ bool ck_mask_at(const unsigned char* p, int idx) {
    unsigned int w0 = *(const unsigned int*)p;
    if ((w0 & 0xFFFFFF00u) != 0u) {
        return p[idx] != 0;                          // int8 bool layout
    } else {
        return ((const int*)p)[idx] != 0;            // int32 layout
    }
}

// 8-wide batched accumulate: 8 independent LDG.128.CG in flight, then FMAs.
__device__ __forceinline__ void batch8(const float4* __restrict__ e4,
                                       const int* __restrict__ toks,
                                       int t0, int j,
                                       float4& acc, float& lenf)
{
    int tk[8];
    #pragma unroll
    for (int i = 0; i < 8; i++) tk[i] = toks[t0 + i];
    float4 v[8];
    #pragma unroll
    for (int i = 0; i < 8; i++) v[i] = __ldcg(&e4[(size_t)tk[i] * D4 + j]);
    #pragma unroll
    for (int i = 0; i < 8; i++) {
        float w = (tk[i] != 0) ? 1.0f : 0.0f;
        acc.x = fmaf(w, v[i].x, acc.x);
        acc.y = fmaf(w, v[i].y, acc.y);
        acc.z = fmaf(w, v[i].z, acc.z);
        acc.w = fmaf(w, v[i].w, acc.w);
        lenf += w;
    }
}

// ---------------------------------------------------------------------------
// Kernel 1: ragged segment-sum pooling, 256 threads/block, branchless,
// explicit 8-wide load batching. __launch_bounds__(256,4) gives ptxas a
// 64-register budget so the batch actually stays in flight.
// Thread layout: j = tid & 63 (float4 column), tq = tid >> 6 (token group).
// Blocks [0, N*K): know pooling (tq handles 16 of 64 tokens, 2 batches).
// Blocks [N*K, N*K+N): ctx pooling (tq handles 64 of 256 tokens, 8 batches).
// ---------------------------------------------------------------------------
__global__ __launch_bounds__(256, 4)
void pool_kernel(const int* __restrict__ src_tokens,
                 const int* __restrict__ know_tokens,
                 const unsigned char* __restrict__ ckm,
                 const float* __restrict__ embed)
{
    __shared__ int    toks[PTC];
    __shared__ float4 part[4][D4];     // 4 KB
    __shared__ float  lenp[4];

    const int tid = threadIdx.x;
    const int j   = tid & 63;
    const int tq  = tid >> 6;
    const int b   = blockIdx.x;
    const float4* __restrict__ e4 = (const float4*)embed;

    float4 acc = make_float4(0.f, 0.f, 0.f, 0.f);
    float  lenf = 0.f;
    float* dst;

    if (b < PN * PK) {
        const int n = b / PK;
        if (tid < PTK) toks[tid] = know_tokens[(size_t)b * PTK + tid];
        __syncthreads();
        const float cmv = ck_mask_at(ckm, n * PK + (b % PK)) ? 1.0f : 0.0f;

        const int t0 = tq * 16;
        batch8(e4, toks, t0,     j, acc, lenf);
        batch8(e4, toks, t0 + 8, j, acc, lenf);

        acc.x *= cmv; acc.y *= cmv; acc.z *= cmv; acc.w *= cmv;
        lenf *= cmv;
        dst = g_know_use + (size_t)b * PD;
    } else {
        const int n = b - PN * PK;
        toks[tid] = src_tokens[n * PTC + tid];
        __syncthreads();

        const int t0 = tq * 64;
        #pragma unroll
        for (int bt = 0; bt < 8; bt++)
            batch8(e4, toks, t0 + bt * 8, j, acc, lenf);

        dst = g_ctx_use + (size_t)n * PD;
    }

    part[tq][j] = acc;
    if (j == 0) lenp[tq] = lenf;
    __syncthreads();

    if (tq == 0) {
        float4 p0 = part[0][j], p1 = part[1][j], p2 = part[2][j], p3 = part[3][j];
        float4 a = make_float4(p0.x + p1.x + p2.x + p3.x,
                               p0.y + p1.y + p2.y + p3.y,
                               p0.z + p1.z + p2.z + p3.z,
                               p0.w + p1.w + p2.w + p3.w);
        float L = lenp[0] + lenp[1] + lenp[2] + lenp[3];
        float s = rsqrtf(256.0f * fmaxf(L, 1.0f));
        ((float4*)dst)[j] = make_float4(a.x * s, a.y * s, a.z * s, a.w * s);
    }
}

// ---------------------------------------------------------------------------
// Kernel 2: ck_attn = know_use . ctx_use, argmax selection, write ck_attn out.
// One block per n, 256 threads (8 warps, warp w handles k = w, w+8, ...).
// ---------------------------------------------------------------------------
__global__ __launch_bounds__(256)
void attn_kernel(const int* __restrict__ cs_ids,
                 const int* __restrict__ use_cs_ids,
                 const unsigned char* __restrict__ ckm,
                 float* __restrict__ out_ck_attn)
{
    const int n = blockIdx.x;
    const int wid = threadIdx.x >> 5;
    const int lane = threadIdx.x & 31;
    __shared__ float scores[PK];

    const float* __restrict__ cu = g_ctx_use + (size_t)n * PD;
    for (int k = wid; k < PK; k += 8) {
        const float* __restrict__ ku = g_know_use + ((size_t)n * PK + k) * PD;
        float p = 0.f;
        #pragma unroll
        for (int i = lane; i < PD; i += 32) p += ku[i] * cu[i];
        #pragma unroll
        for (int o = 16; o; o >>= 1) p += __shfl_xor_sync(0xFFFFFFFFu, p, o);
        if (lane == 0) scores[k] = p;
    }
    __syncthreads();

    if (threadIdx.x == 0) {
        int use = *use_cs_ids;
        int best = 0;
        float bv = -__int_as_float(0x7f800000);  // -inf
        #pragma unroll
        for (int k = 0; k < PK; k++) {
            float v = ck_mask_at(ckm, n * PK + k) ? scores[k] : -__int_as_float(0x7f800000);
            if (v > bv) { bv = v; best = k; }   // first-max (strict >) matches jnp.argmax
        }
        g_cs[n] = use ? cs_ids[n] : best;
    }
    if (threadIdx.x < PK) {
        bool cm = ck_mask_at(ckm, n * PK + threadIdx.x);
        out_ck_attn[n * PK + threadIdx.x] = cm ? scores[threadIdx.x] : 0.0f;
    }
}

// ---------------------------------------------------------------------------
// Kernel 3: build full_enc [N, 320, 256] and full_mask [N, 320]. Branchless.
// 256 threads/block, 4 output rows per block (tid>>6), float4 per thread.
// Streaming stores keep the 21 MB output from evicting embed in L2.
// ---------------------------------------------------------------------------
__global__ __launch_bounds__(256)
void gather_kernel(const int* __restrict__ src_tokens,
                   const int* __restrict__ know_tokens,
                   const unsigned char* __restrict__ ckm,
                   const float* __restrict__ embed,
                   float* __restrict__ out_enc,
                   float* __restrict__ out_mask)
{
    const int tid = threadIdx.x;
    const int j   = tid & 63;
    const int r   = blockIdx.x * 4 + (tid >> 6);   // 0 .. N*320-1
    const int n = r / FULL_T;
    const int t = r % FULL_T;

    int tok;
    bool m;
    if (t < PTK) {
        int cs = g_cs[n];
        tok = know_tokens[((size_t)n * PK + cs) * PTK + t];
        m = (tok != 0) && ck_mask_at(ckm, n * PK + cs);
    } else {
        tok = src_tokens[n * PTC + (t - PTK)];
        m = (tok != 0);
    }

    float w = m ? 1.0f : 0.0f;
    int row = m ? tok : 0;
    float4 v = __ldcg(&((const float4*)embed)[(size_t)row * D4 + j]);
    __stcs(&((float4*)out_enc)[(size_t)r * D4 + j],
           make_float4(w * v.x, w * v.y, w * v.z, w * v.w));
    if (j == 0) out_mask[r] = w;
}

// ---------------------------------------------------------------------------
extern "C" void kernel_launch(void* const* d_in, const int* in_sizes, int n_in,
                              void* d_out, int out_size)
{
    const int*           src_tokens  = (const int*)d_in[0];            // [N,TC]
    const int*           know_tokens = (const int*)d_in[1];            // [N,K,TK]
    const unsigned char* ck_mask     = (const unsigned char*)d_in[2];  // [N,K] bool
    const int*           cs_ids      = (const int*)d_in[3];            // [N]
    const int*           use_cs_ids  = (const int*)d_in[4];            // scalar
    const float*         embed       = (const float*)d_in[5];          // [V,D]

    float* out = (float*)d_out;
    float* out_enc     = out;                                   // N*320*256
    float* out_mask    = out + (size_t)PN * FULL_T * PD;        // N*320
    float* out_ck_attn = out_mask + (size_t)PN * FULL_T;        // N*K

    pool_kernel<<<PN * PK + PN, 256>>>(src_tokens, know_tokens, ck_mask, embed);
    attn_kernel<<<PN, 256>>>(cs_ids, use_cs_ids, ck_mask, out_ck_attn);
    gather_kernel<<<(PN * FULL_T) / 4, 256>>>(src_tokens, know_tokens, ck_mask, embed,
                                              out_enc, out_mask);
}